// round 1
// baseline (speedup 1.0000x reference)
#include <cuda_runtime.h>
#include <math.h>

#define NN   100000
#define NE   1600000
#define INF  128
#define HID  64
#define OUTF 40
#define GRD  8
#define NF   (HID*GRD)   // 512 features per trig branch

// Scratch ping-pong buffers (no cudaMalloc allowed)
__device__ float g_bufA[(size_t)NN * HID];
__device__ float g_bufB[(size_t)NN * HID];

// ---------------------------------------------------------------------------
// h = x @ W_in + b_in      x:[NN,128]  W:[128,64]  -> bufA
// 16 nodes per CTA, 256 threads, each thread does 4 consecutive j via float4 W
// ---------------------------------------------------------------------------
__global__ __launch_bounds__(256) void lin_in_kernel(
    const float* __restrict__ x, const float* __restrict__ W,
    const float* __restrict__ b)
{
    __shared__ float xs[16][INF];
    const int n0  = blockIdx.x * 16;
    const int tid = threadIdx.x;

    for (int idx = tid; idx < 16 * INF; idx += 256) {
        int n = idx >> 7, c = idx & 127;
        xs[n][c] = x[(size_t)(n0 + n) * INF + c];
    }
    __syncthreads();

    const int j4 = (tid & 15) * 4;
    const int ny = tid >> 4;
    const int n  = n0 + ny;

    float a0 = b[j4], a1 = b[j4 + 1], a2 = b[j4 + 2], a3 = b[j4 + 3];
#pragma unroll 8
    for (int i = 0; i < INF; i++) {
        float xv = xs[ny][i];
        float4 w = *reinterpret_cast<const float4*>(W + i * HID + j4);
        a0 += xv * w.x; a1 += xv * w.y; a2 += xv * w.z; a3 += xv * w.w;
    }
    float4 r = make_float4(a0, a1, a2, a3);
    *reinterpret_cast<float4*>(g_bufA + (size_t)n * HID + j4) = r;
}

// ---------------------------------------------------------------------------
// zero a scratch buffer (graph-capturable; avoids needing symbol addresses)
// ---------------------------------------------------------------------------
__global__ __launch_bounds__(256) void zeroB_kernel()
{
    size_t t = (size_t)blockIdx.x * 256 + threadIdx.x;   // float4 index
    float4 z = make_float4(0.f, 0.f, 0.f, 0.f);
    reinterpret_cast<float4*>(g_bufB)[t] = z;
}

// ---------------------------------------------------------------------------
// spmm: out[row[e]] += w[e] * in[col[e]]   (in/out are [NN,64])
// one thread per (edge, 4-feature chunk); vector red scatter (sm_90+)
// ---------------------------------------------------------------------------
__global__ __launch_bounds__(256) void spmm_kernel(
    const int* __restrict__ erow, const int* __restrict__ ecol,
    const float* __restrict__ ew,
    const float* __restrict__ xin, float* __restrict__ xout)
{
    long long t = (long long)blockIdx.x * 256 + threadIdx.x;
    int e = (int)(t >> 4);
    int q = ((int)t & 15) * 4;

    int   c  = ecol[e];
    int   r  = erow[e];
    float wv = ew[e];

    float4 v = *reinterpret_cast<const float4*>(xin + (size_t)c * HID + q);
    float* dst = xout + (size_t)r * HID + q;
    asm volatile("red.global.add.v4.f32 [%0], {%1,%2,%3,%4};"
                 :: "l"(dst), "f"(v.x * wv), "f"(v.y * wv),
                    "f"(v.z * wv), "f"(v.w * wv)
                 : "memory");
}

// ---------------------------------------------------------------------------
// Fourier KAN layer: y[n,j] = sum_{i,k} cos(k x_ni) C0[j,i,k] + sin(..) C1[j,i,k]
// coeff: [2][64][64][8] -> C0/C1 each [j][f], f = i*8+k, 512 per row
// 32 nodes per CTA, 256 threads. Features staged in SMEM [f][node].
// ---------------------------------------------------------------------------
__global__ __launch_bounds__(256) void kan_kernel(
    const float* __restrict__ xin, const float* __restrict__ coeff,
    float* __restrict__ xout)
{
    extern __shared__ float sm[];
    float* sT = sm;              // [64][33] transposed inputs
    float* fc = sm + HID * 33;   // [512][32] cos features
    float* fs = fc + NF * 32;    // [512][32] sin features

    const int n0  = blockIdx.x * 32;
    const int tid = threadIdx.x;

    // load input tile, transpose into SMEM (pad 33 avoids bank conflicts)
    for (int idx = tid; idx < 32 * HID; idx += 256) {
        int n = idx >> 6, i = idx & 63;
        sT[i * 33 + n] = xin[(size_t)(n0 + n) * HID + i];
    }
    __syncthreads();

    // features: 32 nodes x 512 f ; n = lane, f uniform per warp-iteration
    for (int idx = tid; idx < 32 * NF; idx += 256) {
        int n = idx & 31;
        int f = idx >> 5;          // f = i*8 + k
        int i = f >> 3, k = f & 7;
        float ang = sT[i * 33 + n] * (float)(k + 1);
        float sv, cv;
        sincosf(ang, &sv, &cv);
        fc[f * 32 + n] = cv;
        fs[f * 32 + n] = sv;
    }
    __syncthreads();

    // matmul: lane = node, warp w covers j = w + 8*jj
    const int lane = tid & 31;
    const int w    = tid >> 5;
    const float* C0 = coeff;
    const float* C1 = coeff + (size_t)HID * HID * GRD;

    float acc[8];
#pragma unroll
    for (int jj = 0; jj < 8; jj++) acc[jj] = 0.f;

    for (int f = 0; f < NF; f += 4) {
        float c0 = fc[(f + 0) * 32 + lane];
        float c1 = fc[(f + 1) * 32 + lane];
        float c2 = fc[(f + 2) * 32 + lane];
        float c3 = fc[(f + 3) * 32 + lane];
        float s0 = fs[(f + 0) * 32 + lane];
        float s1 = fs[(f + 1) * 32 + lane];
        float s2 = fs[(f + 2) * 32 + lane];
        float s3 = fs[(f + 3) * 32 + lane];
#pragma unroll
        for (int jj = 0; jj < 8; jj++) {
            int j = w + jj * 8;
            float4 a = *reinterpret_cast<const float4*>(C0 + (size_t)j * NF + f);
            float4 b = *reinterpret_cast<const float4*>(C1 + (size_t)j * NF + f);
            acc[jj] += c0 * a.x + c1 * a.y + c2 * a.z + c3 * a.w;
            acc[jj] += s0 * b.x + s1 * b.y + s2 * b.z + s3 * b.w;
        }
    }

#pragma unroll
    for (int jj = 0; jj < 8; jj++)
        xout[(size_t)(n0 + lane) * HID + w + jj * 8] = acc[jj];
}

// ---------------------------------------------------------------------------
// out = log_softmax(h @ W_out)   h:[NN,64]  W_out:[64,40]
// one node per CTA (64 threads; first 40 compute)
// ---------------------------------------------------------------------------
__global__ __launch_bounds__(64) void out_kernel(
    const float* __restrict__ Wout, float* __restrict__ out)
{
    __shared__ float o[OUTF];
    __shared__ float red[2];
    const int n = blockIdx.x;
    const int j = threadIdx.x;

    if (j < OUTF) {
        float acc = 0.f;
        const float* h = g_bufA + (size_t)n * HID;
#pragma unroll 8
        for (int i = 0; i < HID; i++) acc += h[i] * Wout[i * OUTF + j];
        o[j] = acc;
    }
    __syncthreads();
    if (j == 0) {
        float m = -1e30f;
        for (int t = 0; t < OUTF; t++) m = fmaxf(m, o[t]);
        float s = 0.f;
        for (int t = 0; t < OUTF; t++) s += expf(o[t] - m);
        red[0] = m; red[1] = logf(s);
    }
    __syncthreads();
    if (j < OUTF) out[(size_t)n * OUTF + j] = o[j] - red[0] - red[1];
}

// ---------------------------------------------------------------------------
extern "C" void kernel_launch(void* const* d_in, const int* in_sizes, int n_in,
                              void* d_out, int out_size)
{
    const float* x     = (const float*)d_in[0];
    const int*   erow  = (const int*)  d_in[1];
    const int*   ecol  = (const int*)  d_in[2];
    const float* ew    = (const float*)d_in[3];
    const float* W_in  = (const float*)d_in[4];
    const float* b_in  = (const float*)d_in[5];
    const float* c1    = (const float*)d_in[6];
    const float* c2    = (const float*)d_in[7];
    const float* W_out = (const float*)d_in[8];
    float* out = (float*)d_out;

    float *bufA = nullptr, *bufB = nullptr;
    cudaGetSymbolAddress((void**)&bufA, g_bufA);
    cudaGetSymbolAddress((void**)&bufB, g_bufB);

    const int KAN_SMEM = (HID * 33 + 2 * NF * 32) * (int)sizeof(float); // ~139.5 KB
    cudaFuncSetAttribute(kan_kernel,
                         cudaFuncAttributeMaxDynamicSharedMemorySize, KAN_SMEM);

    const int zeroBlocks = (NN * HID / 4) / 256;        // 6250
    const int spmmBlocks = (int)(((long long)NE * 16) / 256); // 100000

    // 1. lin_in -> bufA
    lin_in_kernel<<<NN / 16, 256>>>(x, W_in, b_in);
    // 2. spmm(bufA) -> bufB
    zeroB_kernel<<<zeroBlocks, 256>>>();
    spmm_kernel<<<spmmBlocks, 256>>>(erow, ecol, ew, bufA, bufB);
    // 3. KAN1(bufB) -> bufA
    kan_kernel<<<NN / 32, 256, KAN_SMEM>>>(bufB, c1, bufA);
    // 4. spmm(bufA) -> bufB
    zeroB_kernel<<<zeroBlocks, 256>>>();
    spmm_kernel<<<spmmBlocks, 256>>>(erow, ecol, ew, bufA, bufB);
    // 5. KAN2(bufB) -> bufA
    kan_kernel<<<NN / 32, 256, KAN_SMEM>>>(bufB, c2, bufA);
    // 6. lin_out + log_softmax -> d_out
    out_kernel<<<NN, 64>>>(W_out, out);
}

// round 2
// speedup vs baseline: 4.0495x; 4.0495x over previous
#include <cuda_runtime.h>
#include <math.h>

#define NN    100000
#define NNP   100096          // padded to multiple of 128
#define NE    1600000
#define INF   128
#define HID   64
#define OUTF  40
#define GRD   8
#define NFT   1024            // features: f = i*16 + branch*8 + k  (cos k=0..7, sin k=0..7)
#define KT    64              // f per tile
#define KTI   (NFT/KT)        // 16 tiles

typedef unsigned long long ull;

// Scratch (no cudaMalloc allowed)
__device__ float g_bufA[(size_t)NNP * HID];
__device__ float g_bufB[(size_t)NNP * HID];
__device__ float g_Bt[2][NFT * HID];   // transposed coeffs: Bt[f*64 + j]

// ---------------- f32x2 helpers ----------------
__device__ __forceinline__ ull pk2(float s) {
    ull d; unsigned u = __float_as_uint(s);
    asm("mov.b64 %0, {%1,%1};" : "=l"(d) : "r"(u));
    return d;
}
__device__ __forceinline__ void fma2(ull& d, ull a, ull b) {
    asm("fma.rn.f32x2 %0, %1, %2, %0;" : "+l"(d) : "l"(a), "l"(b));
}
__device__ __forceinline__ float2 up2(ull v) {
    unsigned lo, hi;
    asm("mov.b64 {%0,%1}, %2;" : "=r"(lo), "=r"(hi) : "l"(v));
    return make_float2(__uint_as_float(lo), __uint_as_float(hi));
}

// ---------------------------------------------------------------------------
// Transpose coeff [2][64][64][8] -> Bt[1024][64], f = i*16 + b*8 + k
// ---------------------------------------------------------------------------
__global__ __launch_bounds__(256) void transpose_coeff(
    const float* __restrict__ c, float* __restrict__ Bt)
{
    int idx = blockIdx.x * 256 + threadIdx.x;   // over 1024*64
    int j = idx & 63;
    int f = idx >> 6;
    int i = f >> 4, b = (f >> 3) & 1, k = f & 7;
    Bt[idx] = c[(((size_t)b * HID + j) * HID + i) * GRD + k];
}

// ---------------------------------------------------------------------------
// h = x @ W_in + b_in   -> bufA (rows < NN)
// ---------------------------------------------------------------------------
__global__ __launch_bounds__(256) void lin_in_kernel(
    const float* __restrict__ x, const float* __restrict__ W,
    const float* __restrict__ b)
{
    __shared__ float xs[16][INF];
    const int n0  = blockIdx.x * 16;
    const int tid = threadIdx.x;

    for (int idx = tid; idx < 16 * INF; idx += 256) {
        int n = idx >> 7, c = idx & 127;
        xs[n][c] = x[(size_t)(n0 + n) * INF + c];
    }
    __syncthreads();

    const int j4 = (tid & 15) * 4;
    const int ny = tid >> 4;
    const int n  = n0 + ny;

    float a0 = b[j4], a1 = b[j4 + 1], a2 = b[j4 + 2], a3 = b[j4 + 3];
#pragma unroll 8
    for (int i = 0; i < INF; i++) {
        float xv = xs[ny][i];
        float4 w = *reinterpret_cast<const float4*>(W + i * HID + j4);
        a0 += xv * w.x; a1 += xv * w.y; a2 += xv * w.z; a3 += xv * w.w;
    }
    *reinterpret_cast<float4*>(g_bufA + (size_t)n * HID + j4) =
        make_float4(a0, a1, a2, a3);
}

// ---------------------------------------------------------------------------
__global__ __launch_bounds__(256) void zeroB_kernel()
{
    size_t t = (size_t)blockIdx.x * 256 + threadIdx.x;   // float4 index
    reinterpret_cast<float4*>(g_bufB)[t] = make_float4(0.f, 0.f, 0.f, 0.f);
}

// ---------------------------------------------------------------------------
// spmm: out[row[e]] += w[e] * in[col[e]]   (in/out [NNP,64])
// one thread per (edge, 4-feature chunk); vector red scatter
// ---------------------------------------------------------------------------
__global__ __launch_bounds__(256) void spmm_kernel(
    const int* __restrict__ erow, const int* __restrict__ ecol,
    const float* __restrict__ ew,
    const float* __restrict__ xin, float* __restrict__ xout)
{
    long long t = (long long)blockIdx.x * 256 + threadIdx.x;
    int e = (int)(t >> 4);
    int q = ((int)t & 15) * 4;

    int   c  = ecol[e];
    int   r  = erow[e];
    float wv = ew[e];

    float4 v = *reinterpret_cast<const float4*>(xin + (size_t)c * HID + q);
    float* dst = xout + (size_t)r * HID + q;
    asm volatile("red.global.add.v4.f32 [%0], {%1,%2,%3,%4};"
                 :: "l"(dst), "f"(v.x * wv), "f"(v.y * wv),
                    "f"(v.z * wv), "f"(v.w * wv)
                 : "memory");
}

// ---------------------------------------------------------------------------
// Fourier KAN as SMEM-tiled GEMM with f32x2 packed math.
// CTA: 128 nodes x 64 j. 128 threads, thread tile = 8 nodes (4 pairs) x 8 j.
// SMEM: sx [64][129] staged inputs (transposed), ft [64 f][128 n] features,
//       ct [64 f][64 j] coeff tile.
// ---------------------------------------------------------------------------
__global__ __launch_bounds__(128) void kan_kernel(
    const float* __restrict__ xin, const float* __restrict__ Bt,
    float* __restrict__ xout)
{
    extern __shared__ float sm[];
    float* sx = sm;                       // 64*129 = 8256 floats
    float* ft = sx + HID * 129;           // 64*128 = 8192 floats
    float* ct = ft + KT * 128;            // 64*64  = 4096 floats

    const int tid = threadIdx.x;
    const int n0  = blockIdx.x * 128;
    const int ng  = tid & 15;             // node-pair group
    const int jg  = tid >> 4;             // j group (0..7)

    // ---- stage inputs transposed: sx[i*129 + n] = xin[(n0+n)*64 + i] ----
#pragma unroll
    for (int r = 0; r < 64; r++) {
        int idx = r * 128 + tid;          // coalesced over global
        int i = idx & 63;
        int n = idx >> 6;
        sx[i * 129 + n] = xin[(size_t)(n0 + n) * HID + i];
    }
    __syncthreads();

    ull acc[8][4];
#pragma unroll
    for (int jj = 0; jj < 8; jj++)
#pragma unroll
        for (int p = 0; p < 4; p++) acc[jj][p] = 0ULL;

    for (int kt = 0; kt < KTI; kt++) {
        // ---- features via Chebyshev recurrence: 4 i-values per tile ----
#pragma unroll
        for (int r = 0; r < 4; r++) {
            int idx = tid + 128 * r;      // 512 (n, ii) pairs
            int n  = idx & 127;
            int ii = idx >> 7;            // 0..3
            float xv = sx[(kt * 4 + ii) * 129 + n];
            float s1, c1;
            sincosf(xv, &s1, &c1);
            float* fcp = ft + (ii * 16) * 128 + n;   // cos rows
            float* fsp = fcp + 8 * 128;              // sin rows
            float twoc = 2.f * c1;
            float cp = 1.f, spv = 0.f, ck = c1, sk = s1;
            fcp[0] = c1; fsp[0] = s1;
#pragma unroll
            for (int k = 1; k < 8; k++) {
                float cn = twoc * ck - cp;
                float sn = twoc * sk - spv;
                cp = ck; spv = sk; ck = cn; sk = sn;
                fcp[k * 128] = ck; fsp[k * 128] = sk;
            }
        }
        // ---- coeff tile: contiguous 16 KB from Bt ----
        {
            const float4* src = reinterpret_cast<const float4*>(Bt + kt * (KT * HID));
            float4* dst = reinterpret_cast<float4*>(ct);
#pragma unroll
            for (int r = 0; r < 8; r++) dst[tid + 128 * r] = src[tid + 128 * r];
        }
        __syncthreads();

        // ---- MMA inner loop ----
#pragma unroll 4
        for (int f = 0; f < KT; f++) {
            const float* ftf = ft + f * 128;
            ull x0 = *reinterpret_cast<const ull*>(ftf + (ng     ) * 2);
            ull x1 = *reinterpret_cast<const ull*>(ftf + (ng + 16) * 2);
            ull x2 = *reinterpret_cast<const ull*>(ftf + (ng + 32) * 2);
            ull x3 = *reinterpret_cast<const ull*>(ftf + (ng + 48) * 2);
            const float* ctf = ct + f * HID + jg * 8;
            float4 cA = *reinterpret_cast<const float4*>(ctf);
            float4 cB = *reinterpret_cast<const float4*>(ctf + 4);
            ull c0 = pk2(cA.x), c1 = pk2(cA.y), c2 = pk2(cA.z), c3 = pk2(cA.w);
            ull c4 = pk2(cB.x), c5 = pk2(cB.y), c6 = pk2(cB.z), c7 = pk2(cB.w);
            fma2(acc[0][0], c0, x0); fma2(acc[0][1], c0, x1); fma2(acc[0][2], c0, x2); fma2(acc[0][3], c0, x3);
            fma2(acc[1][0], c1, x0); fma2(acc[1][1], c1, x1); fma2(acc[1][2], c1, x2); fma2(acc[1][3], c1, x3);
            fma2(acc[2][0], c2, x0); fma2(acc[2][1], c2, x1); fma2(acc[2][2], c2, x2); fma2(acc[2][3], c2, x3);
            fma2(acc[3][0], c3, x0); fma2(acc[3][1], c3, x1); fma2(acc[3][2], c3, x2); fma2(acc[3][3], c3, x3);
            fma2(acc[4][0], c4, x0); fma2(acc[4][1], c4, x1); fma2(acc[4][2], c4, x2); fma2(acc[4][3], c4, x3);
            fma2(acc[5][0], c5, x0); fma2(acc[5][1], c5, x1); fma2(acc[5][2], c5, x2); fma2(acc[5][3], c5, x3);
            fma2(acc[6][0], c6, x0); fma2(acc[6][1], c6, x1); fma2(acc[6][2], c6, x2); fma2(acc[6][3], c6, x3);
            fma2(acc[7][0], c7, x0); fma2(acc[7][1], c7, x1); fma2(acc[7][2], c7, x2); fma2(acc[7][3], c7, x3);
        }
        __syncthreads();
    }

    // ---- write back ----
#pragma unroll
    for (int p = 0; p < 4; p++) {
        int node = n0 + (ng + p * 16) * 2;
        float r0[8], r1[8];
#pragma unroll
        for (int jj = 0; jj < 8; jj++) {
            float2 v = up2(acc[jj][p]);
            r0[jj] = v.x; r1[jj] = v.y;
        }
        float4* d0 = reinterpret_cast<float4*>(xout + (size_t)node * HID + jg * 8);
        d0[0] = make_float4(r0[0], r0[1], r0[2], r0[3]);
        d0[1] = make_float4(r0[4], r0[5], r0[6], r0[7]);
        float4* d1 = reinterpret_cast<float4*>(xout + (size_t)(node + 1) * HID + jg * 8);
        d1[0] = make_float4(r1[0], r1[1], r1[2], r1[3]);
        d1[1] = make_float4(r1[4], r1[5], r1[6], r1[7]);
    }
}

// ---------------------------------------------------------------------------
// out = log_softmax(h @ W_out). One warp per node; 8 nodes per CTA.
// ---------------------------------------------------------------------------
__global__ __launch_bounds__(256) void out_kernel(
    const float* __restrict__ Wout, float* __restrict__ out)
{
    const int n    = blockIdx.x * 8 + (threadIdx.x >> 5);
    const int lane = threadIdx.x & 31;
    const float* h = g_bufA + (size_t)n * HID;

    float o0 = 0.f, o1 = 0.f;
#pragma unroll 8
    for (int i = 0; i < HID; i++) {
        float hv = __ldg(h + i);
        o0 += hv * Wout[i * OUTF + lane];
        if (lane < 8) o1 += hv * Wout[i * OUTF + 32 + lane];
    }

    float m = (lane < 8) ? fmaxf(o0, o1) : o0;
#pragma unroll
    for (int off = 16; off; off >>= 1)
        m = fmaxf(m, __shfl_xor_sync(0xFFFFFFFFu, m, off));

    float e = expf(o0 - m) + ((lane < 8) ? expf(o1 - m) : 0.f);
#pragma unroll
    for (int off = 16; off; off >>= 1)
        e += __shfl_xor_sync(0xFFFFFFFFu, e, off);

    float ls = m + logf(e);
    out[(size_t)n * OUTF + lane] = o0 - ls;
    if (lane < 8) out[(size_t)n * OUTF + 32 + lane] = o1 - ls;
}

// ---------------------------------------------------------------------------
extern "C" void kernel_launch(void* const* d_in, const int* in_sizes, int n_in,
                              void* d_out, int out_size)
{
    const float* x     = (const float*)d_in[0];
    const int*   erow  = (const int*)  d_in[1];
    const int*   ecol  = (const int*)  d_in[2];
    const float* ew    = (const float*)d_in[3];
    const float* W_in  = (const float*)d_in[4];
    const float* b_in  = (const float*)d_in[5];
    const float* c1    = (const float*)d_in[6];
    const float* c2    = (const float*)d_in[7];
    const float* W_out = (const float*)d_in[8];
    float* out = (float*)d_out;

    float *bufA = nullptr, *bufB = nullptr, *Bt = nullptr;
    cudaGetSymbolAddress((void**)&bufA, g_bufA);
    cudaGetSymbolAddress((void**)&bufB, g_bufB);
    cudaGetSymbolAddress((void**)&Bt,   g_Bt);

    const int KAN_SMEM = (HID * 129 + KT * 128 + KT * HID) * (int)sizeof(float); // ~80.6 KB
    cudaFuncSetAttribute(kan_kernel,
                         cudaFuncAttributeMaxDynamicSharedMemorySize, KAN_SMEM);

    const int zeroBlocks = (NNP * HID / 4) / 256;             // 6256
    const int spmmBlocks = (int)(((long long)NE * 16) / 256); // 100000
    const int kanBlocks  = NNP / 128;                         // 782

    // 0. transpose coeffs (tiny)
    transpose_coeff<<<256, 256>>>(c1, Bt);
    transpose_coeff<<<256, 256>>>(c2, Bt + NFT * HID);
    // 1. lin_in -> bufA
    lin_in_kernel<<<NN / 16, 256>>>(x, W_in, b_in);
    // 2. spmm(bufA) -> bufB
    zeroB_kernel<<<zeroBlocks, 256>>>();
    spmm_kernel<<<spmmBlocks, 256>>>(erow, ecol, ew, bufA, bufB);
    // 3. KAN1(bufB) -> bufA
    kan_kernel<<<kanBlocks, 128, KAN_SMEM>>>(bufB, Bt, bufA);
    // 4. spmm(bufA) -> bufB
    zeroB_kernel<<<zeroBlocks, 256>>>();
    spmm_kernel<<<spmmBlocks, 256>>>(erow, ecol, ew, bufA, bufB);
    // 5. KAN2(bufB) -> bufA
    kan_kernel<<<kanBlocks, 128, KAN_SMEM>>>(bufB, Bt + NFT * HID, bufA);
    // 6. lin_out + log_softmax -> d_out
    out_kernel<<<NN / 8, 256>>>(W_out, out);
}